// round 1
// baseline (speedup 1.0000x reference)
#include <cuda_runtime.h>
#include <math.h>

#define BB 4
#define SS 2048
#define DD 1024
#define HH 16
#define HDIM 64
#define MM (BB*SS)   // 8192 rows

// Scratch: Q, K, V, attention-out in (b, s, d) layout. 4 x 32MB device globals.
__device__ float g_Q[(size_t)MM * DD];
__device__ float g_K[(size_t)MM * DD];
__device__ float g_V[(size_t)MM * DD];
__device__ float g_O[(size_t)MM * DD];

// ---------------------------------------------------------------------------
// C[M,N] = A[M,K] @ W[K,N] + bias[N]
// 64x64 block tile, BK=16, 256 threads, 4x4 register tile per thread.
// ---------------------------------------------------------------------------
__global__ __launch_bounds__(256) void gemm_bias64(
    const float* __restrict__ A, const float* __restrict__ W,
    const float* __restrict__ bias, float* __restrict__ C,
    int M, int N, int K)
{
    __shared__ float As[16][68];   // As[k][m]  (A transposed in smem)
    __shared__ float Bs[16][68];   // Bs[k][n]

    const int tid = threadIdx.x;
    const int tx  = tid & 15;      // 0..15 -> n direction
    const int ty  = tid >> 4;      // 0..15 -> m direction
    const int m0  = blockIdx.y << 6;
    const int n0  = blockIdx.x << 6;

    // load mapping
    const int lar = tid >> 2;      // A row within tile (0..63)
    const int lac = tid & 3;       // A col group (x4)
    const int lbr = tid >> 4;      // B row within tile (0..15)
    const int lbc = tid & 15;      // B col group (x4)

    float acc[4][4] = {};

    for (int k0 = 0; k0 < K; k0 += 16) {
        float4 av = *(const float4*)(A + (size_t)(m0 + lar) * K + k0 + lac * 4);
        float4 bv = *(const float4*)(W + (size_t)(k0 + lbr) * N + n0 + lbc * 4);
        __syncthreads();
        As[lac * 4 + 0][lar] = av.x;
        As[lac * 4 + 1][lar] = av.y;
        As[lac * 4 + 2][lar] = av.z;
        As[lac * 4 + 3][lar] = av.w;
        *(float4*)&Bs[lbr][lbc * 4] = bv;
        __syncthreads();
        #pragma unroll
        for (int kk = 0; kk < 16; kk++) {
            float4 a = *(const float4*)&As[kk][ty * 4];   // broadcast across tx
            float4 b = *(const float4*)&Bs[kk][tx * 4];
            acc[0][0] += a.x*b.x; acc[0][1] += a.x*b.y; acc[0][2] += a.x*b.z; acc[0][3] += a.x*b.w;
            acc[1][0] += a.y*b.x; acc[1][1] += a.y*b.y; acc[1][2] += a.y*b.z; acc[1][3] += a.y*b.w;
            acc[2][0] += a.z*b.x; acc[2][1] += a.z*b.y; acc[2][2] += a.z*b.z; acc[2][3] += a.z*b.w;
            acc[3][0] += a.w*b.x; acc[3][1] += a.w*b.y; acc[3][2] += a.w*b.z; acc[3][3] += a.w*b.w;
        }
    }

    float4 bb = *(const float4*)(bias + n0 + tx * 4);
    #pragma unroll
    for (int i = 0; i < 4; i++) {
        float4 o;
        o.x = acc[i][0] + bb.x;
        o.y = acc[i][1] + bb.y;
        o.z = acc[i][2] + bb.z;
        o.w = acc[i][3] + bb.w;
        *(float4*)(C + (size_t)(m0 + ty * 4 + i) * N + n0 + tx * 4) = o;
    }
}

// ---------------------------------------------------------------------------
// Flash attention (causal), fp32. One block = one 64-row query tile of one
// (batch, head). 256 threads, 4x4 register tile for both S=QK^T and O=PV.
// ---------------------------------------------------------------------------
__device__ __forceinline__ float redmax16(float v) {
    v = fmaxf(v, __shfl_xor_sync(0xffffffffu, v, 1));
    v = fmaxf(v, __shfl_xor_sync(0xffffffffu, v, 2));
    v = fmaxf(v, __shfl_xor_sync(0xffffffffu, v, 4));
    v = fmaxf(v, __shfl_xor_sync(0xffffffffu, v, 8));
    return v;
}
__device__ __forceinline__ float redsum16(float v) {
    v += __shfl_xor_sync(0xffffffffu, v, 1);
    v += __shfl_xor_sync(0xffffffffu, v, 2);
    v += __shfl_xor_sync(0xffffffffu, v, 4);
    v += __shfl_xor_sync(0xffffffffu, v, 8);
    return v;
}

#define ATT_PITCH 68

__global__ __launch_bounds__(256) void attn_causal64(
    const float* __restrict__ Q, const float* __restrict__ K,
    const float* __restrict__ V, float* __restrict__ O)
{
    extern __shared__ float sm[];
    float* Qs = sm;                       // [HDIM][64+pad]  (transposed: [hd][q])
    float* Ks = Qs + HDIM * ATT_PITCH;    // [HDIM][64+pad]  (transposed: [hd][k])
    float* Ps = Ks + HDIM * ATT_PITCH;    // [64][64+pad]    (P[q][k])
    float* Vs = Ps + 64 * ATT_PITCH;      // [64][64+pad]    (V[k][hd])

    const int tid = threadIdx.x;
    const int tx  = tid & 15;
    const int ty  = tid >> 4;
    const int qt  = blockIdx.x;           // query tile 0..31
    const int h   = blockIdx.y;
    const int b   = blockIdx.z;
    const int q0  = qt * 64;
    const size_t row_base = (size_t)b * SS;
    const int col0 = h * HDIM;

    // Load Q tile transposed into smem: Qs[hd][q]
    #pragma unroll
    for (int i = 0; i < 4; i++) {
        int lin = tid + i * 256;          // 0..1023
        int r   = lin >> 4;               // row 0..63
        int c4  = lin & 15;               // float4 group
        float4 v = *(const float4*)(Q + (row_base + q0 + r) * DD + col0 + c4 * 4);
        Qs[(c4 * 4 + 0) * ATT_PITCH + r] = v.x;
        Qs[(c4 * 4 + 1) * ATT_PITCH + r] = v.y;
        Qs[(c4 * 4 + 2) * ATT_PITCH + r] = v.z;
        Qs[(c4 * 4 + 3) * ATT_PITCH + r] = v.w;
    }

    float m_run[4], l_run[4];
    float acc[4][4] = {};
    #pragma unroll
    for (int i = 0; i < 4; i++) { m_run[i] = -INFINITY; l_run[i] = 0.f; }

    for (int kt = 0; kt <= qt; kt++) {
        const int k0 = kt * 64;
        __syncthreads();   // previous iter done with Ks/Vs/Ps
        // Load K tile transposed Ks[hd][k], V tile Vs[k][hd]
        #pragma unroll
        for (int i = 0; i < 4; i++) {
            int lin = tid + i * 256;
            int r   = lin >> 4;
            int c4  = lin & 15;
            float4 kv = *(const float4*)(K + (row_base + k0 + r) * DD + col0 + c4 * 4);
            Ks[(c4 * 4 + 0) * ATT_PITCH + r] = kv.x;
            Ks[(c4 * 4 + 1) * ATT_PITCH + r] = kv.y;
            Ks[(c4 * 4 + 2) * ATT_PITCH + r] = kv.z;
            Ks[(c4 * 4 + 3) * ATT_PITCH + r] = kv.w;
            float4 vv = *(const float4*)(V + (row_base + k0 + r) * DD + col0 + c4 * 4);
            *(float4*)&Vs[r * ATT_PITCH + c4 * 4] = vv;
        }
        __syncthreads();

        // S = Q K^T (4x4 per thread), inner dim = hd (64)
        float s[4][4] = {};
        #pragma unroll
        for (int kk = 0; kk < HDIM; kk++) {
            float4 a = *(const float4*)&Qs[kk * ATT_PITCH + ty * 4];  // broadcast
            float4 c = *(const float4*)&Ks[kk * ATT_PITCH + tx * 4];
            s[0][0] += a.x*c.x; s[0][1] += a.x*c.y; s[0][2] += a.x*c.z; s[0][3] += a.x*c.w;
            s[1][0] += a.y*c.x; s[1][1] += a.y*c.y; s[1][2] += a.y*c.z; s[1][3] += a.y*c.w;
            s[2][0] += a.z*c.x; s[2][1] += a.z*c.y; s[2][2] += a.z*c.z; s[2][3] += a.z*c.w;
            s[3][0] += a.w*c.x; s[3][1] += a.w*c.y; s[3][2] += a.w*c.z; s[3][3] += a.w*c.w;
        }

        // scale + causal mask (only the diagonal tile can be partially masked)
        const float sc = 0.125f;   // 1/sqrt(64)
        if (kt == qt) {
            #pragma unroll
            for (int i = 0; i < 4; i++) {
                int qg = q0 + ty * 4 + i;
                #pragma unroll
                for (int j = 0; j < 4; j++) {
                    int kg = k0 + tx * 4 + j;
                    s[i][j] = (kg > qg) ? -1e30f : s[i][j] * sc;
                }
            }
        } else {
            #pragma unroll
            for (int i = 0; i < 4; i++)
                #pragma unroll
                for (int j = 0; j < 4; j++)
                    s[i][j] *= sc;
        }

        // online softmax per row (16 lanes per row share state consistently)
        #pragma unroll
        for (int i = 0; i < 4; i++) {
            float mloc = fmaxf(fmaxf(s[i][0], s[i][1]), fmaxf(s[i][2], s[i][3]));
            float mnew = fmaxf(m_run[i], redmax16(mloc));
            float corr = expf(m_run[i] - mnew);
            float p0 = expf(s[i][0] - mnew);
            float p1 = expf(s[i][1] - mnew);
            float p2 = expf(s[i][2] - mnew);
            float p3 = expf(s[i][3] - mnew);
            float lsum = redsum16(p0 + p1 + p2 + p3);
            l_run[i] = l_run[i] * corr + lsum;
            m_run[i] = mnew;
            #pragma unroll
            for (int j = 0; j < 4; j++) acc[i][j] *= corr;
            // stash P into smem for the PV matmul
            Ps[(ty * 4 + i) * ATT_PITCH + tx * 4 + 0] = p0;
            Ps[(ty * 4 + i) * ATT_PITCH + tx * 4 + 1] = p1;
            Ps[(ty * 4 + i) * ATT_PITCH + tx * 4 + 2] = p2;
            Ps[(ty * 4 + i) * ATT_PITCH + tx * 4 + 3] = p3;
        }
        __syncthreads();

        // O += P V  (inner dim = k over 64)
        #pragma unroll
        for (int kk = 0; kk < 64; kk++) {
            float4 a;
            a.x = Ps[(ty * 4 + 0) * ATT_PITCH + kk];
            a.y = Ps[(ty * 4 + 1) * ATT_PITCH + kk];
            a.z = Ps[(ty * 4 + 2) * ATT_PITCH + kk];
            a.w = Ps[(ty * 4 + 3) * ATT_PITCH + kk];
            float4 c = *(const float4*)&Vs[kk * ATT_PITCH + tx * 4];
            acc[0][0] += a.x*c.x; acc[0][1] += a.x*c.y; acc[0][2] += a.x*c.z; acc[0][3] += a.x*c.w;
            acc[1][0] += a.y*c.x; acc[1][1] += a.y*c.y; acc[1][2] += a.y*c.z; acc[1][3] += a.y*c.w;
            acc[2][0] += a.z*c.x; acc[2][1] += a.z*c.y; acc[2][2] += a.z*c.z; acc[2][3] += a.z*c.w;
            acc[3][0] += a.w*c.x; acc[3][1] += a.w*c.y; acc[3][2] += a.w*c.z; acc[3][3] += a.w*c.w;
        }
    }

    // normalize and store (b, s, d) layout
    #pragma unroll
    for (int i = 0; i < 4; i++) {
        float inv = 1.0f / l_run[i];
        float4 o;
        o.x = acc[i][0] * inv;
        o.y = acc[i][1] * inv;
        o.z = acc[i][2] * inv;
        o.w = acc[i][3] * inv;
        *(float4*)(O + (row_base + q0 + ty * 4 + i) * DD + col0 + tx * 4) = o;
    }
}

// ---------------------------------------------------------------------------
extern "C" void kernel_launch(void* const* d_in, const int* in_sizes, int n_in,
                              void* d_out, int out_size)
{
    const float* x  = (const float*)d_in[0];
    const float* Wq = (const float*)d_in[1];
    const float* bq = (const float*)d_in[2];
    const float* Wk = (const float*)d_in[3];
    const float* bk = (const float*)d_in[4];
    const float* Wv = (const float*)d_in[5];
    const float* bv = (const float*)d_in[6];
    const float* Wp = (const float*)d_in[7];
    const float* bp = (const float*)d_in[8];
    float* out = (float*)d_out;

    float *Qp, *Kp, *Vp, *Op;
    cudaGetSymbolAddress((void**)&Qp, g_Q);
    cudaGetSymbolAddress((void**)&Kp, g_K);
    cudaGetSymbolAddress((void**)&Vp, g_V);
    cudaGetSymbolAddress((void**)&Op, g_O);

    dim3 gemm_grid(DD / 64, MM / 64);   // (16, 128)
    gemm_bias64<<<gemm_grid, 256>>>(x, Wq, bq, Qp, MM, DD, DD);
    gemm_bias64<<<gemm_grid, 256>>>(x, Wk, bk, Kp, MM, DD, DD);
    gemm_bias64<<<gemm_grid, 256>>>(x, Wv, bv, Vp, MM, DD, DD);

    static bool attr_set = false;
    const int att_smem = 4 * 64 * ATT_PITCH * (int)sizeof(float);  // ~68KB
    if (!attr_set) {
        cudaFuncSetAttribute(attn_causal64,
                             cudaFuncAttributeMaxDynamicSharedMemorySize, att_smem);
        attr_set = true;
    }
    dim3 attn_grid(SS / 64, HH, BB);    // (32, 16, 4)
    attn_causal64<<<attn_grid, 256, att_smem>>>(Qp, Kp, Vp, Op);

    gemm_bias64<<<gemm_grid, 256>>>(Op, Wp, bp, out, MM, DD, DD);
}

// round 2
// speedup vs baseline: 1.7819x; 1.7819x over previous
#include <cuda_runtime.h>
#include <math.h>

#define BB 4
#define SS 2048
#define DD 1024
#define HH 16
#define HDIM 64
#define MM (BB*SS)   // 8192 rows

// Scratch: Q, K, V, attention-out in (b, s, d) layout.
__device__ float g_Q[(size_t)MM * DD];
__device__ float g_K[(size_t)MM * DD];
__device__ float g_V[(size_t)MM * DD];
__device__ float g_O[(size_t)MM * DD];

// ---------------------------------------------------------------------------
// TF32 tensor-core GEMM: C[M,N] = A[M,K] @ W[K,N] + bias[N]
// 128x128 block tile, BK=32, 256 threads (8 warps, 4m x 2n), warp tile 32x64.
// mma.sync.m16n8k8.tf32, fp32 accumulate. Inputs rounded to TF32 at STS time.
// ---------------------------------------------------------------------------
__device__ __forceinline__ unsigned f2tf32(float x) {
    unsigned y;
    asm("cvt.rna.tf32.f32 %0, %1;" : "=r"(y) : "f"(x));
    return y;
}

__device__ __forceinline__ void mma_tf32(float c[4], const unsigned a[4],
                                         unsigned b0, unsigned b1) {
    asm volatile(
        "mma.sync.aligned.m16n8k8.row.col.f32.tf32.tf32.f32 "
        "{%0,%1,%2,%3}, {%4,%5,%6,%7}, {%8,%9}, {%0,%1,%2,%3};"
        : "+f"(c[0]), "+f"(c[1]), "+f"(c[2]), "+f"(c[3])
        : "r"(a[0]), "r"(a[1]), "r"(a[2]), "r"(a[3]), "r"(b0), "r"(b1));
}

#define APITCH 36    // floats; row stride 144B (16B aligned, conflict-free frag LDS)
#define BPITCH 136   // floats; row stride 544B (16B aligned, conflict-free frag LDS)

__global__ __launch_bounds__(256, 2) void gemm_tf32(
    const float* __restrict__ A, const float* __restrict__ W,
    const float* __restrict__ bias, float* __restrict__ C,
    int M, int N, int K)
{
    __shared__ float As[128 * APITCH];   // As[m][k]
    __shared__ float Bs[32 * BPITCH];    // Bs[k][n]

    const int tid  = threadIdx.x;
    const int warp = tid >> 5;
    const int lane = tid & 31;
    const int grp  = lane >> 2;    // 0..7
    const int tig  = lane & 3;     // 0..3
    const int wm   = (warp >> 1) * 32;   // warp m offset in tile
    const int wn   = (warp & 1) * 64;    // warp n offset in tile
    const int m0   = blockIdx.y << 7;
    const int n0   = blockIdx.x << 7;

    // global load mapping
    const int ar = tid >> 3;       // A row 0..31 (stride 32, 4 passes)
    const int ac = (tid & 7) * 4;  // A col group
    const int br = tid >> 5;       // B row 0..7 (stride 8, 4 passes)
    const int bc = (tid & 31) * 4; // B col group

    float acc[2][8][4] = {};
    float4 aReg[4], bReg[4];

    // prologue: load tile 0
    #pragma unroll
    for (int i = 0; i < 4; i++) {
        aReg[i] = *(const float4*)(A + (size_t)(m0 + ar + i * 32) * K + ac);
        bReg[i] = *(const float4*)(W + (size_t)(br + i * 8) * N + n0 + bc);
    }

    const int NT = K >> 5;   // 32 iters
    for (int it = 0; it < NT; it++) {
        __syncthreads();
        // store current tile to smem with TF32 rounding
        #pragma unroll
        for (int i = 0; i < 4; i++) {
            float4 t;
            t.x = __uint_as_float(f2tf32(aReg[i].x));
            t.y = __uint_as_float(f2tf32(aReg[i].y));
            t.z = __uint_as_float(f2tf32(aReg[i].z));
            t.w = __uint_as_float(f2tf32(aReg[i].w));
            *(float4*)&As[(ar + i * 32) * APITCH + ac] = t;
            float4 u;
            u.x = __uint_as_float(f2tf32(bReg[i].x));
            u.y = __uint_as_float(f2tf32(bReg[i].y));
            u.z = __uint_as_float(f2tf32(bReg[i].z));
            u.w = __uint_as_float(f2tf32(bReg[i].w));
            *(float4*)&Bs[(br + i * 8) * BPITCH + bc] = u;
        }
        __syncthreads();

        // prefetch next tile (overlaps with mma compute below)
        if (it + 1 < NT) {
            const int k0n = (it + 1) << 5;
            #pragma unroll
            for (int i = 0; i < 4; i++) {
                aReg[i] = *(const float4*)(A + (size_t)(m0 + ar + i * 32) * K + k0n + ac);
                bReg[i] = *(const float4*)(W + (size_t)(k0n + br + i * 8) * N + n0 + bc);
            }
        }

        // compute: 4 k-steps of 8
        #pragma unroll
        for (int ks = 0; ks < 4; ks++) {
            const int kb = ks * 8;
            unsigned a[2][4];
            #pragma unroll
            for (int fm = 0; fm < 2; fm++) {
                const int mb = wm + fm * 16;
                a[fm][0] = __float_as_uint(As[(mb + grp) * APITCH + kb + tig]);
                a[fm][1] = __float_as_uint(As[(mb + grp + 8) * APITCH + kb + tig]);
                a[fm][2] = __float_as_uint(As[(mb + grp) * APITCH + kb + tig + 4]);
                a[fm][3] = __float_as_uint(As[(mb + grp + 8) * APITCH + kb + tig + 4]);
            }
            #pragma unroll
            for (int fn = 0; fn < 8; fn++) {
                const int nb = wn + fn * 8;
                unsigned b0 = __float_as_uint(Bs[(kb + tig) * BPITCH + nb + grp]);
                unsigned b1 = __float_as_uint(Bs[(kb + tig + 4) * BPITCH + nb + grp]);
                mma_tf32(acc[0][fn], a[0], b0, b1);
                mma_tf32(acc[1][fn], a[1], b0, b1);
            }
        }
    }

    // epilogue: bias add + store (float2 per half-fragment)
    #pragma unroll
    for (int fm = 0; fm < 2; fm++) {
        #pragma unroll
        for (int fn = 0; fn < 8; fn++) {
            const int r0 = m0 + wm + fm * 16 + grp;
            const int c0 = n0 + wn + fn * 8 + tig * 2;
            float2 bb = *(const float2*)(bias + c0);
            float2 o0, o1;
            o0.x = acc[fm][fn][0] + bb.x;
            o0.y = acc[fm][fn][1] + bb.y;
            o1.x = acc[fm][fn][2] + bb.x;
            o1.y = acc[fm][fn][3] + bb.y;
            *(float2*)(C + (size_t)r0 * N + c0) = o0;
            *(float2*)(C + (size_t)(r0 + 8) * N + c0) = o1;
        }
    }
}

// ---------------------------------------------------------------------------
// Flash attention (causal), fp32 — unchanged from R0.
// ---------------------------------------------------------------------------
__device__ __forceinline__ float redmax16(float v) {
    v = fmaxf(v, __shfl_xor_sync(0xffffffffu, v, 1));
    v = fmaxf(v, __shfl_xor_sync(0xffffffffu, v, 2));
    v = fmaxf(v, __shfl_xor_sync(0xffffffffu, v, 4));
    v = fmaxf(v, __shfl_xor_sync(0xffffffffu, v, 8));
    return v;
}
__device__ __forceinline__ float redsum16(float v) {
    v += __shfl_xor_sync(0xffffffffu, v, 1);
    v += __shfl_xor_sync(0xffffffffu, v, 2);
    v += __shfl_xor_sync(0xffffffffu, v, 4);
    v += __shfl_xor_sync(0xffffffffu, v, 8);
    return v;
}

#define ATT_PITCH 68

__global__ __launch_bounds__(256) void attn_causal64(
    const float* __restrict__ Q, const float* __restrict__ K,
    const float* __restrict__ V, float* __restrict__ O)
{
    extern __shared__ float sm[];
    float* Qs = sm;
    float* Ks = Qs + HDIM * ATT_PITCH;
    float* Ps = Ks + HDIM * ATT_PITCH;
    float* Vs = Ps + 64 * ATT_PITCH;

    const int tid = threadIdx.x;
    const int tx  = tid & 15;
    const int ty  = tid >> 4;
    const int qt  = blockIdx.x;
    const int h   = blockIdx.y;
    const int b   = blockIdx.z;
    const int q0  = qt * 64;
    const size_t row_base = (size_t)b * SS;
    const int col0 = h * HDIM;

    #pragma unroll
    for (int i = 0; i < 4; i++) {
        int lin = tid + i * 256;
        int r   = lin >> 4;
        int c4  = lin & 15;
        float4 v = *(const float4*)(Q + (row_base + q0 + r) * DD + col0 + c4 * 4);
        Qs[(c4 * 4 + 0) * ATT_PITCH + r] = v.x;
        Qs[(c4 * 4 + 1) * ATT_PITCH + r] = v.y;
        Qs[(c4 * 4 + 2) * ATT_PITCH + r] = v.z;
        Qs[(c4 * 4 + 3) * ATT_PITCH + r] = v.w;
    }

    float m_run[4], l_run[4];
    float acc[4][4] = {};
    #pragma unroll
    for (int i = 0; i < 4; i++) { m_run[i] = -INFINITY; l_run[i] = 0.f; }

    for (int kt = 0; kt <= qt; kt++) {
        const int k0 = kt * 64;
        __syncthreads();
        #pragma unroll
        for (int i = 0; i < 4; i++) {
            int lin = tid + i * 256;
            int r   = lin >> 4;
            int c4  = lin & 15;
            float4 kv = *(const float4*)(K + (row_base + k0 + r) * DD + col0 + c4 * 4);
            Ks[(c4 * 4 + 0) * ATT_PITCH + r] = kv.x;
            Ks[(c4 * 4 + 1) * ATT_PITCH + r] = kv.y;
            Ks[(c4 * 4 + 2) * ATT_PITCH + r] = kv.z;
            Ks[(c4 * 4 + 3) * ATT_PITCH + r] = kv.w;
            float4 vv = *(const float4*)(V + (row_base + k0 + r) * DD + col0 + c4 * 4);
            *(float4*)&Vs[r * ATT_PITCH + c4 * 4] = vv;
        }
        __syncthreads();

        float s[4][4] = {};
        #pragma unroll
        for (int kk = 0; kk < HDIM; kk++) {
            float4 a = *(const float4*)&Qs[kk * ATT_PITCH + ty * 4];
            float4 c = *(const float4*)&Ks[kk * ATT_PITCH + tx * 4];
            s[0][0] += a.x*c.x; s[0][1] += a.x*c.y; s[0][2] += a.x*c.z; s[0][3] += a.x*c.w;
            s[1][0] += a.y*c.x; s[1][1] += a.y*c.y; s[1][2] += a.y*c.z; s[1][3] += a.y*c.w;
            s[2][0] += a.z*c.x; s[2][1] += a.z*c.y; s[2][2] += a.z*c.z; s[2][3] += a.z*c.w;
            s[3][0] += a.w*c.x; s[3][1] += a.w*c.y; s[3][2] += a.w*c.z; s[3][3] += a.w*c.w;
        }

        const float sc = 0.125f;
        if (kt == qt) {
            #pragma unroll
            for (int i = 0; i < 4; i++) {
                int qg = q0 + ty * 4 + i;
                #pragma unroll
                for (int j = 0; j < 4; j++) {
                    int kg = k0 + tx * 4 + j;
                    s[i][j] = (kg > qg) ? -1e30f : s[i][j] * sc;
                }
            }
        } else {
            #pragma unroll
            for (int i = 0; i < 4; i++)
                #pragma unroll
                for (int j = 0; j < 4; j++)
                    s[i][j] *= sc;
        }

        #pragma unroll
        for (int i = 0; i < 4; i++) {
            float mloc = fmaxf(fmaxf(s[i][0], s[i][1]), fmaxf(s[i][2], s[i][3]));
            float mnew = fmaxf(m_run[i], redmax16(mloc));
            float corr = expf(m_run[i] - mnew);
            float p0 = expf(s[i][0] - mnew);
            float p1 = expf(s[i][1] - mnew);
            float p2 = expf(s[i][2] - mnew);
            float p3 = expf(s[i][3] - mnew);
            float lsum = redsum16(p0 + p1 + p2 + p3);
            l_run[i] = l_run[i] * corr + lsum;
            m_run[i] = mnew;
            #pragma unroll
            for (int j = 0; j < 4; j++) acc[i][j] *= corr;
            Ps[(ty * 4 + i) * ATT_PITCH + tx * 4 + 0] = p0;
            Ps[(ty * 4 + i) * ATT_PITCH + tx * 4 + 1] = p1;
            Ps[(ty * 4 + i) * ATT_PITCH + tx * 4 + 2] = p2;
            Ps[(ty * 4 + i) * ATT_PITCH + tx * 4 + 3] = p3;
        }
        __syncthreads();

        #pragma unroll
        for (int kk = 0; kk < 64; kk++) {
            float4 a;
            a.x = Ps[(ty * 4 + 0) * ATT_PITCH + kk];
            a.y = Ps[(ty * 4 + 1) * ATT_PITCH + kk];
            a.z = Ps[(ty * 4 + 2) * ATT_PITCH + kk];
            a.w = Ps[(ty * 4 + 3) * ATT_PITCH + kk];
            float4 c = *(const float4*)&Vs[kk * ATT_PITCH + tx * 4];
            acc[0][0] += a.x*c.x; acc[0][1] += a.x*c.y; acc[0][2] += a.x*c.z; acc[0][3] += a.x*c.w;
            acc[1][0] += a.y*c.x; acc[1][1] += a.y*c.y; acc[1][2] += a.y*c.z; acc[1][3] += a.y*c.w;
            acc[2][0] += a.z*c.x; acc[2][1] += a.z*c.y; acc[2][2] += a.z*c.z; acc[2][3] += a.z*c.w;
            acc[3][0] += a.w*c.x; acc[3][1] += a.w*c.y; acc[3][2] += a.w*c.z; acc[3][3] += a.w*c.w;
        }
    }

    #pragma unroll
    for (int i = 0; i < 4; i++) {
        float inv = 1.0f / l_run[i];
        float4 o;
        o.x = acc[i][0] * inv;
        o.y = acc[i][1] * inv;
        o.z = acc[i][2] * inv;
        o.w = acc[i][3] * inv;
        *(float4*)(O + (row_base + q0 + ty * 4 + i) * DD + col0 + tx * 4) = o;
    }
}

// ---------------------------------------------------------------------------
extern "C" void kernel_launch(void* const* d_in, const int* in_sizes, int n_in,
                              void* d_out, int out_size)
{
    const float* x  = (const float*)d_in[0];
    const float* Wq = (const float*)d_in[1];
    const float* bq = (const float*)d_in[2];
    const float* Wk = (const float*)d_in[3];
    const float* bk = (const float*)d_in[4];
    const float* Wv = (const float*)d_in[5];
    const float* bv = (const float*)d_in[6];
    const float* Wp = (const float*)d_in[7];
    const float* bp = (const float*)d_in[8];
    float* out = (float*)d_out;

    float *Qp, *Kp, *Vp, *Op;
    cudaGetSymbolAddress((void**)&Qp, g_Q);
    cudaGetSymbolAddress((void**)&Kp, g_K);
    cudaGetSymbolAddress((void**)&Vp, g_V);
    cudaGetSymbolAddress((void**)&Op, g_O);

    dim3 gemm_grid(DD / 128, MM / 128);   // (8, 64)
    gemm_tf32<<<gemm_grid, 256>>>(x, Wq, bq, Qp, MM, DD, DD);
    gemm_tf32<<<gemm_grid, 256>>>(x, Wk, bk, Kp, MM, DD, DD);
    gemm_tf32<<<gemm_grid, 256>>>(x, Wv, bv, Vp, MM, DD, DD);

    static bool attr_set = false;
    const int att_smem = 4 * 64 * ATT_PITCH * (int)sizeof(float);
    if (!attr_set) {
        cudaFuncSetAttribute(attn_causal64,
                             cudaFuncAttributeMaxDynamicSharedMemorySize, att_smem);
        attr_set = true;
    }
    dim3 attn_grid(SS / 64, HH, BB);    // (32, 16, 4)
    attn_causal64<<<attn_grid, 256, att_smem>>>(Qp, Kp, Vp, Op);

    gemm_tf32<<<gemm_grid, 256>>>(Op, Wp, bp, out, MM, DD, DD);
}

// round 3
// speedup vs baseline: 3.0318x; 1.7014x over previous
#include <cuda_runtime.h>
#include <math.h>

#define BB 4
#define SS 2048
#define DD 1024
#define HH 16
#define HDIM 64
#define MM (BB*SS)   // 8192 rows

// Scratch: Q, K, V, attention-out in (b, s, d) layout.
__device__ float g_Q[(size_t)MM * DD];
__device__ float g_K[(size_t)MM * DD];
__device__ float g_V[(size_t)MM * DD];
__device__ float g_O[(size_t)MM * DD];

// ---------------------------------------------------------------------------
__device__ __forceinline__ unsigned f2tf32(float x) {
    unsigned y;
    asm("cvt.rna.tf32.f32 %0, %1;" : "=r"(y) : "f"(x));
    return y;
}
__device__ __forceinline__ float4 tf32x4(float4 v) {
    float4 t;
    t.x = __uint_as_float(f2tf32(v.x));
    t.y = __uint_as_float(f2tf32(v.y));
    t.z = __uint_as_float(f2tf32(v.z));
    t.w = __uint_as_float(f2tf32(v.w));
    return t;
}
__device__ __forceinline__ void mma_tf32(float c[4], const unsigned a[4],
                                         unsigned b0, unsigned b1) {
    asm volatile(
        "mma.sync.aligned.m16n8k8.row.col.f32.tf32.tf32.f32 "
        "{%0,%1,%2,%3}, {%4,%5,%6,%7}, {%8,%9}, {%0,%1,%2,%3};"
        : "+f"(c[0]), "+f"(c[1]), "+f"(c[2]), "+f"(c[3])
        : "r"(a[0]), "r"(a[1]), "r"(a[2]), "r"(a[3]), "r"(b0), "r"(b1));
}

// ---------------------------------------------------------------------------
// TF32 tensor-core GEMM: C[M,N] = A[M,K] @ W[K,N] + bias[N]   (same as R1)
// ---------------------------------------------------------------------------
#define APITCH 36
#define BPITCH 136

__global__ __launch_bounds__(256, 2) void gemm_tf32(
    const float* __restrict__ A, const float* __restrict__ W,
    const float* __restrict__ bias, float* __restrict__ C,
    int M, int N, int K)
{
    __shared__ float As[128 * APITCH];   // As[m][k]
    __shared__ float Bs[32 * BPITCH];    // Bs[k][n]

    const int tid  = threadIdx.x;
    const int warp = tid >> 5;
    const int lane = tid & 31;
    const int grp  = lane >> 2;
    const int tig  = lane & 3;
    const int wm   = (warp >> 1) * 32;
    const int wn   = (warp & 1) * 64;
    const int m0   = blockIdx.y << 7;
    const int n0   = blockIdx.x << 7;

    const int ar = tid >> 3;
    const int ac = (tid & 7) * 4;
    const int br = tid >> 5;
    const int bc = (tid & 31) * 4;

    float acc[2][8][4] = {};
    float4 aReg[4], bReg[4];

    #pragma unroll
    for (int i = 0; i < 4; i++) {
        aReg[i] = *(const float4*)(A + (size_t)(m0 + ar + i * 32) * K + ac);
        bReg[i] = *(const float4*)(W + (size_t)(br + i * 8) * N + n0 + bc);
    }

    const int NT = K >> 5;
    for (int it = 0; it < NT; it++) {
        __syncthreads();
        #pragma unroll
        for (int i = 0; i < 4; i++) {
            *(float4*)&As[(ar + i * 32) * APITCH + ac] = tf32x4(aReg[i]);
            *(float4*)&Bs[(br + i * 8) * BPITCH + bc] = tf32x4(bReg[i]);
        }
        __syncthreads();

        if (it + 1 < NT) {
            const int k0n = (it + 1) << 5;
            #pragma unroll
            for (int i = 0; i < 4; i++) {
                aReg[i] = *(const float4*)(A + (size_t)(m0 + ar + i * 32) * K + k0n + ac);
                bReg[i] = *(const float4*)(W + (size_t)(k0n + br + i * 8) * N + n0 + bc);
            }
        }

        #pragma unroll
        for (int ks = 0; ks < 4; ks++) {
            const int kb = ks * 8;
            unsigned a[2][4];
            #pragma unroll
            for (int fm = 0; fm < 2; fm++) {
                const int mb = wm + fm * 16;
                a[fm][0] = __float_as_uint(As[(mb + grp) * APITCH + kb + tig]);
                a[fm][1] = __float_as_uint(As[(mb + grp + 8) * APITCH + kb + tig]);
                a[fm][2] = __float_as_uint(As[(mb + grp) * APITCH + kb + tig + 4]);
                a[fm][3] = __float_as_uint(As[(mb + grp + 8) * APITCH + kb + tig + 4]);
            }
            #pragma unroll
            for (int fn = 0; fn < 8; fn++) {
                const int nb = wn + fn * 8;
                unsigned b0 = __float_as_uint(Bs[(kb + tig) * BPITCH + nb + grp]);
                unsigned b1 = __float_as_uint(Bs[(kb + tig + 4) * BPITCH + nb + grp]);
                mma_tf32(acc[0][fn], a[0], b0, b1);
                mma_tf32(acc[1][fn], a[1], b0, b1);
            }
        }
    }

    #pragma unroll
    for (int fm = 0; fm < 2; fm++) {
        #pragma unroll
        for (int fn = 0; fn < 8; fn++) {
            const int r0 = m0 + wm + fm * 16 + grp;
            const int c0 = n0 + wn + fn * 8 + tig * 2;
            float2 bb = *(const float2*)(bias + c0);
            float2 o0, o1;
            o0.x = acc[fm][fn][0] + bb.x;
            o0.y = acc[fm][fn][1] + bb.y;
            o1.x = acc[fm][fn][2] + bb.x;
            o1.y = acc[fm][fn][3] + bb.y;
            *(float2*)(C + (size_t)r0 * N + c0) = o0;
            *(float2*)(C + (size_t)(r0 + 8) * N + c0) = o1;
        }
    }
}

// ---------------------------------------------------------------------------
// Flash attention (causal) on tensor cores (TF32 mma).
// Block = 128 queries of one (b,h). 8 warps x 16 query rows. 64-key tiles.
// Q/K/V in smem in NATURAL [row][col] layout (mma row.col B-frag = B[k][n]).
// ---------------------------------------------------------------------------
#define QP 68   // pitch for Qs [128][64]
#define KP 68   // pitch for Ks [64][64]
#define VP 68   // pitch for Vs [64][64]
#define PP 68   // pitch for per-warp Ps [16][64]

#define ATT_SMEM ((128 + 64 + 64 + 128) * 68 * 4)   // 104448 bytes

__global__ __launch_bounds__(256, 2) void attn_tc(
    const float* __restrict__ Q, const float* __restrict__ K,
    const float* __restrict__ V, float* __restrict__ O)
{
    extern __shared__ float sm[];
    float* Qs = sm;                      // [128][QP]
    float* Ks = Qs + 128 * QP;           // [64][KP]
    float* Vs = Ks + 64 * KP;            // [64][VP]
    float* Psall = Vs + 64 * VP;         // 8 x [16][PP]

    const int tid  = threadIdx.x;
    const int warp = tid >> 5;
    const int lane = tid & 31;
    const int grp  = lane >> 2;          // 0..7
    const int tig  = lane & 3;           // 0..3
    const int wm   = warp * 16;          // warp query-row offset in tile
    float* Ps = Psall + warp * 16 * PP;

    const int qt = gridDim.x - 1 - blockIdx.x;  // long tiles first
    const int h  = blockIdx.y;
    const int b  = blockIdx.z;
    const int q0 = qt * 128;
    const size_t row_base = (size_t)b * SS;
    const int col0 = h * HDIM;

    // Load Q tile [128][64] (natural layout, tf32-rounded)
    #pragma unroll
    for (int i = 0; i < 8; i++) {
        int lin = tid + i * 256;         // 0..2047
        int r   = lin >> 4;
        int c4  = (lin & 15) * 4;
        float4 v = *(const float4*)(Q + (row_base + q0 + r) * DD + col0 + c4);
        *(float4*)&Qs[r * QP + c4] = tf32x4(v);
    }

    const int r0g = q0 + wm + grp;       // global query row (lower)
    const int r1g = r0g + 8;             // global query row (upper)

    float m0r = -INFINITY, m1r = -INFINITY;
    float l0r = 0.f, l1r = 0.f;
    float acc[8][4] = {};

    const int n_kt = 2 * qt + 2;
    for (int kt = 0; kt < n_kt; kt++) {
        const int k0 = kt * 64;
        __syncthreads();                 // protect Ks/Vs from previous iter
        // Load K,V tiles [64][64] natural layout
        #pragma unroll
        for (int i = 0; i < 4; i++) {
            int lin = tid + i * 256;
            int r   = lin >> 4;
            int c4  = (lin & 15) * 4;
            float4 kv = *(const float4*)(K + (row_base + k0 + r) * DD + col0 + c4);
            *(float4*)&Ks[r * KP + c4] = tf32x4(kv);
            float4 vv = *(const float4*)(V + (row_base + k0 + r) * DD + col0 + c4);
            *(float4*)&Vs[r * VP + c4] = tf32x4(vv);
        }
        __syncthreads();

        // ---- S = Q K^T : 8 n-frags of 8 keys, 8 k-steps over hd ----
        float s[8][4] = {};
        #pragma unroll
        for (int ks = 0; ks < 8; ks++) {
            const int kb = ks * 8;
            unsigned a[4];
            a[0] = __float_as_uint(Qs[(wm + grp) * QP + kb + tig]);
            a[1] = __float_as_uint(Qs[(wm + grp + 8) * QP + kb + tig]);
            a[2] = __float_as_uint(Qs[(wm + grp) * QP + kb + tig + 4]);
            a[3] = __float_as_uint(Qs[(wm + grp + 8) * QP + kb + tig + 4]);
            #pragma unroll
            for (int fn = 0; fn < 8; fn++) {
                unsigned b0 = __float_as_uint(Ks[(fn * 8 + grp) * KP + kb + tig]);
                unsigned b1 = __float_as_uint(Ks[(fn * 8 + grp) * KP + kb + tig + 4]);
                mma_tf32(s[fn], a, b0, b1);
            }
        }

        // ---- scale + causal mask ----
        const float sc = 0.125f;
        if (k0 + 63 > q0) {
            #pragma unroll
            for (int fn = 0; fn < 8; fn++) {
                int kg = k0 + fn * 8 + tig * 2;
                s[fn][0] = (kg     > r0g) ? -1e30f : s[fn][0] * sc;
                s[fn][1] = (kg + 1 > r0g) ? -1e30f : s[fn][1] * sc;
                s[fn][2] = (kg     > r1g) ? -1e30f : s[fn][2] * sc;
                s[fn][3] = (kg + 1 > r1g) ? -1e30f : s[fn][3] * sc;
            }
        } else {
            #pragma unroll
            for (int fn = 0; fn < 8; fn++) {
                s[fn][0] *= sc; s[fn][1] *= sc; s[fn][2] *= sc; s[fn][3] *= sc;
            }
        }

        // ---- online softmax (rows grp / grp+8; quad lanes share a row) ----
        float m0 = -INFINITY, m1 = -INFINITY;
        #pragma unroll
        for (int fn = 0; fn < 8; fn++) {
            m0 = fmaxf(m0, fmaxf(s[fn][0], s[fn][1]));
            m1 = fmaxf(m1, fmaxf(s[fn][2], s[fn][3]));
        }
        m0 = fmaxf(m0, __shfl_xor_sync(0xffffffffu, m0, 1));
        m0 = fmaxf(m0, __shfl_xor_sync(0xffffffffu, m0, 2));
        m1 = fmaxf(m1, __shfl_xor_sync(0xffffffffu, m1, 1));
        m1 = fmaxf(m1, __shfl_xor_sync(0xffffffffu, m1, 2));

        float mn0 = fmaxf(m0r, m0);
        float mn1 = fmaxf(m1r, m1);
        float corr0 = __expf(m0r - mn0);
        float corr1 = __expf(m1r - mn1);

        float ls0 = 0.f, ls1 = 0.f;
        #pragma unroll
        for (int fn = 0; fn < 8; fn++) {
            float p0 = __expf(s[fn][0] - mn0);
            float p1 = __expf(s[fn][1] - mn0);
            float p2 = __expf(s[fn][2] - mn1);
            float p3 = __expf(s[fn][3] - mn1);
            ls0 += p0 + p1;
            ls1 += p2 + p3;
            const int c = fn * 8 + tig * 2;
            Ps[grp * PP + c]           = __uint_as_float(f2tf32(p0));
            Ps[grp * PP + c + 1]       = __uint_as_float(f2tf32(p1));
            Ps[(grp + 8) * PP + c]     = __uint_as_float(f2tf32(p2));
            Ps[(grp + 8) * PP + c + 1] = __uint_as_float(f2tf32(p3));
        }
        ls0 += __shfl_xor_sync(0xffffffffu, ls0, 1);
        ls0 += __shfl_xor_sync(0xffffffffu, ls0, 2);
        ls1 += __shfl_xor_sync(0xffffffffu, ls1, 1);
        ls1 += __shfl_xor_sync(0xffffffffu, ls1, 2);

        l0r = l0r * corr0 + ls0;
        l1r = l1r * corr1 + ls1;
        m0r = mn0;
        m1r = mn1;

        #pragma unroll
        for (int fn = 0; fn < 8; fn++) {
            acc[fn][0] *= corr0; acc[fn][1] *= corr0;
            acc[fn][2] *= corr1; acc[fn][3] *= corr1;
        }
        __syncwarp();   // Ps visible within warp

        // ---- O += P V : k = 64 keys, n = 64 hd ----
        #pragma unroll
        for (int ks = 0; ks < 8; ks++) {
            const int kb = ks * 8;
            unsigned a[4];
            a[0] = __float_as_uint(Ps[grp * PP + kb + tig]);
            a[1] = __float_as_uint(Ps[(grp + 8) * PP + kb + tig]);
            a[2] = __float_as_uint(Ps[grp * PP + kb + tig + 4]);
            a[3] = __float_as_uint(Ps[(grp + 8) * PP + kb + tig + 4]);
            #pragma unroll
            for (int fn = 0; fn < 8; fn++) {
                unsigned b0 = __float_as_uint(Vs[(kb + tig) * VP + fn * 8 + grp]);
                unsigned b1 = __float_as_uint(Vs[(kb + tig + 4) * VP + fn * 8 + grp]);
                mma_tf32(acc[fn], a, b0, b1);
            }
        }
        __syncwarp();   // done reading Ps before next iter overwrites
    }

    // ---- normalize + store ----
    float inv0 = 1.0f / l0r;
    float inv1 = 1.0f / l1r;
    #pragma unroll
    for (int fn = 0; fn < 8; fn++) {
        const int c0 = col0 + fn * 8 + tig * 2;
        float2 o0, o1;
        o0.x = acc[fn][0] * inv0;
        o0.y = acc[fn][1] * inv0;
        o1.x = acc[fn][2] * inv1;
        o1.y = acc[fn][3] * inv1;
        *(float2*)(O + (row_base + r0g) * DD + c0) = o0;
        *(float2*)(O + (row_base + r1g) * DD + c0) = o1;
    }
}

// ---------------------------------------------------------------------------
extern "C" void kernel_launch(void* const* d_in, const int* in_sizes, int n_in,
                              void* d_out, int out_size)
{
    const float* x  = (const float*)d_in[0];
    const float* Wq = (const float*)d_in[1];
    const float* bq = (const float*)d_in[2];
    const float* Wk = (const float*)d_in[3];
    const float* bk = (const float*)d_in[4];
    const float* Wv = (const float*)d_in[5];
    const float* bv = (const float*)d_in[6];
    const float* Wp = (const float*)d_in[7];
    const float* bp = (const float*)d_in[8];
    float* out = (float*)d_out;

    float *Qp, *Kp, *Vp, *Op;
    cudaGetSymbolAddress((void**)&Qp, g_Q);
    cudaGetSymbolAddress((void**)&Kp, g_K);
    cudaGetSymbolAddress((void**)&Vp, g_V);
    cudaGetSymbolAddress((void**)&Op, g_O);

    dim3 gemm_grid(DD / 128, MM / 128);   // (8, 64)
    gemm_tf32<<<gemm_grid, 256>>>(x, Wq, bq, Qp, MM, DD, DD);
    gemm_tf32<<<gemm_grid, 256>>>(x, Wk, bk, Kp, MM, DD, DD);
    gemm_tf32<<<gemm_grid, 256>>>(x, Wv, bv, Vp, MM, DD, DD);

    static bool attr_set = false;
    if (!attr_set) {
        cudaFuncSetAttribute(attn_tc,
                             cudaFuncAttributeMaxDynamicSharedMemorySize, ATT_SMEM);
        attr_set = true;
    }
    dim3 attn_grid(SS / 128, HH, BB);    // (16, 16, 4)
    attn_tc<<<attn_grid, 256, ATT_SMEM>>>(Qp, Kp, Vp, Op);

    gemm_tf32<<<gemm_grid, 256>>>(Op, Wp, bp, out, MM, DD, DD);
}

// round 4
// speedup vs baseline: 3.3982x; 1.1208x over previous
#include <cuda_runtime.h>
#include <math.h>

#define BB 4
#define SS 2048
#define DD 1024
#define HH 16
#define HDIM 64
#define MM (BB*SS)   // 8192 rows

// Scratch: Q, K, V, attention-out in (b, s, d) layout.
__device__ float g_Q[(size_t)MM * DD];
__device__ float g_K[(size_t)MM * DD];
__device__ float g_V[(size_t)MM * DD];
__device__ float g_O[(size_t)MM * DD];

// ---------------------------------------------------------------------------
__device__ __forceinline__ unsigned f2tf32(float x) {
    unsigned y;
    asm("cvt.rna.tf32.f32 %0, %1;" : "=r"(y) : "f"(x));
    return y;
}
__device__ __forceinline__ float4 tf32x4(float4 v) {
    float4 t;
    t.x = __uint_as_float(f2tf32(v.x));
    t.y = __uint_as_float(f2tf32(v.y));
    t.z = __uint_as_float(f2tf32(v.z));
    t.w = __uint_as_float(f2tf32(v.w));
    return t;
}
__device__ __forceinline__ void mma_tf32(float c[4], const unsigned a[4],
                                         unsigned b0, unsigned b1) {
    asm volatile(
        "mma.sync.aligned.m16n8k8.row.col.f32.tf32.tf32.f32 "
        "{%0,%1,%2,%3}, {%4,%5,%6,%7}, {%8,%9}, {%0,%1,%2,%3};"
        : "+f"(c[0]), "+f"(c[1]), "+f"(c[2]), "+f"(c[3])
        : "r"(a[0]), "r"(a[1]), "r"(a[2]), "r"(a[3]), "r"(b0), "r"(b1));
}

// ---------------------------------------------------------------------------
// TF32 tensor-core GEMM: C[M,N] = A[M,K] @ W[K,N] + bias[N]   (unchanged)
// ---------------------------------------------------------------------------
#define APITCH 36
#define BPITCH 136

__global__ __launch_bounds__(256, 2) void gemm_tf32(
    const float* __restrict__ A, const float* __restrict__ W,
    const float* __restrict__ bias, float* __restrict__ C,
    int M, int N, int K)
{
    __shared__ float As[128 * APITCH];   // As[m][k]
    __shared__ float Bs[32 * BPITCH];    // Bs[k][n]

    const int tid  = threadIdx.x;
    const int warp = tid >> 5;
    const int lane = tid & 31;
    const int grp  = lane >> 2;
    const int tig  = lane & 3;
    const int wm   = (warp >> 1) * 32;
    const int wn   = (warp & 1) * 64;
    const int m0   = blockIdx.y << 7;
    const int n0   = blockIdx.x << 7;

    const int ar = tid >> 3;
    const int ac = (tid & 7) * 4;
    const int br = tid >> 5;
    const int bc = (tid & 31) * 4;

    float acc[2][8][4] = {};
    float4 aReg[4], bReg[4];

    #pragma unroll
    for (int i = 0; i < 4; i++) {
        aReg[i] = *(const float4*)(A + (size_t)(m0 + ar + i * 32) * K + ac);
        bReg[i] = *(const float4*)(W + (size_t)(br + i * 8) * N + n0 + bc);
    }

    const int NT = K >> 5;
    for (int it = 0; it < NT; it++) {
        __syncthreads();
        #pragma unroll
        for (int i = 0; i < 4; i++) {
            *(float4*)&As[(ar + i * 32) * APITCH + ac] = tf32x4(aReg[i]);
            *(float4*)&Bs[(br + i * 8) * BPITCH + bc] = tf32x4(bReg[i]);
        }
        __syncthreads();

        if (it + 1 < NT) {
            const int k0n = (it + 1) << 5;
            #pragma unroll
            for (int i = 0; i < 4; i++) {
                aReg[i] = *(const float4*)(A + (size_t)(m0 + ar + i * 32) * K + k0n + ac);
                bReg[i] = *(const float4*)(W + (size_t)(k0n + br + i * 8) * N + n0 + bc);
            }
        }

        #pragma unroll
        for (int ks = 0; ks < 4; ks++) {
            const int kb = ks * 8;
            unsigned a[2][4];
            #pragma unroll
            for (int fm = 0; fm < 2; fm++) {
                const int mb = wm + fm * 16;
                a[fm][0] = __float_as_uint(As[(mb + grp) * APITCH + kb + tig]);
                a[fm][1] = __float_as_uint(As[(mb + grp + 8) * APITCH + kb + tig]);
                a[fm][2] = __float_as_uint(As[(mb + grp) * APITCH + kb + tig + 4]);
                a[fm][3] = __float_as_uint(As[(mb + grp + 8) * APITCH + kb + tig + 4]);
            }
            #pragma unroll
            for (int fn = 0; fn < 8; fn++) {
                const int nb = wn + fn * 8;
                unsigned b0 = __float_as_uint(Bs[(kb + tig) * BPITCH + nb + grp]);
                unsigned b1 = __float_as_uint(Bs[(kb + tig + 4) * BPITCH + nb + grp]);
                mma_tf32(acc[0][fn], a[0], b0, b1);
                mma_tf32(acc[1][fn], a[1], b0, b1);
            }
        }
    }

    #pragma unroll
    for (int fm = 0; fm < 2; fm++) {
        #pragma unroll
        for (int fn = 0; fn < 8; fn++) {
            const int r0 = m0 + wm + fm * 16 + grp;
            const int c0 = n0 + wn + fn * 8 + tig * 2;
            float2 bb = *(const float2*)(bias + c0);
            float2 o0, o1;
            o0.x = acc[fm][fn][0] + bb.x;
            o0.y = acc[fm][fn][1] + bb.y;
            o1.x = acc[fm][fn][2] + bb.x;
            o1.y = acc[fm][fn][3] + bb.y;
            *(float2*)(C + (size_t)r0 * N + c0) = o0;
            *(float2*)(C + (size_t)(r0 + 8) * N + c0) = o1;
        }
    }
}

// ---------------------------------------------------------------------------
// Flash attention (causal) on tensor cores (TF32 mma).
// Block = 128 queries of one (b,h). 4 warps x 32 query rows (2 m16 frags
// sharing every B fragment). 64-key tiles. Natural [row][col] smem layouts.
// ---------------------------------------------------------------------------
#define QP 68
#define KP 68
#define VP 68
#define PP 68

#define ATT_SMEM ((128 + 64 + 64 + 128) * 68 * 4)   // 104448 bytes

__global__ __launch_bounds__(128, 2) void attn_tc(
    const float* __restrict__ Q, const float* __restrict__ K,
    const float* __restrict__ V, float* __restrict__ O)
{
    extern __shared__ float sm[];
    float* Qs = sm;                      // [128][QP]
    float* Ks = Qs + 128 * QP;           // [64][KP]
    float* Vs = Ks + 64 * KP;            // [64][VP]
    float* Psall = Vs + 64 * VP;         // 4 x [32][PP]

    const int tid  = threadIdx.x;
    const int warp = tid >> 5;
    const int lane = tid & 31;
    const int grp  = lane >> 2;          // 0..7
    const int tig  = lane & 3;           // 0..3
    const int wm   = warp * 32;          // warp query-row offset in tile
    float* Ps = Psall + warp * 32 * PP;

    const int qt = gridDim.x - 1 - blockIdx.x;  // long tiles first
    const int h  = blockIdx.y;
    const int b  = blockIdx.z;
    const int q0 = qt * 128;
    const size_t row_base = (size_t)b * SS;
    const int col0 = h * HDIM;

    // Load Q tile [128][64] (natural layout, tf32-rounded)
    #pragma unroll
    for (int i = 0; i < 16; i++) {
        int lin = tid + i * 128;         // 0..2047
        int r   = lin >> 4;
        int c4  = (lin & 15) * 4;
        float4 v = *(const float4*)(Q + (row_base + q0 + r) * DD + col0 + c4);
        *(float4*)&Qs[r * QP + c4] = tf32x4(v);
    }

    // per-thread rows: fm in {0,1}, sub-row a = grp, b = grp+8 (within frag)
    float mr[2][2], lr[2][2];
    #pragma unroll
    for (int fm = 0; fm < 2; fm++) {
        mr[fm][0] = -INFINITY; mr[fm][1] = -INFINITY;
        lr[fm][0] = 0.f;       lr[fm][1] = 0.f;
    }
    float acc[2][8][4] = {};

    const int n_kt = 2 * qt + 2;
    for (int kt = 0; kt < n_kt; kt++) {
        const int k0 = kt * 64;
        __syncthreads();                 // protect Ks/Vs from previous iter
        // Load K,V tiles [64][64] natural layout
        #pragma unroll
        for (int i = 0; i < 8; i++) {
            int lin = tid + i * 128;
            int r   = lin >> 4;
            int c4  = (lin & 15) * 4;
            float4 kv = *(const float4*)(K + (row_base + k0 + r) * DD + col0 + c4);
            *(float4*)&Ks[r * KP + c4] = tf32x4(kv);
            float4 vv = *(const float4*)(V + (row_base + k0 + r) * DD + col0 + c4);
            *(float4*)&Vs[r * VP + c4] = tf32x4(vv);
        }
        __syncthreads();

        // ---- S = Q K^T : 2 m-frags x 8 n-frags, 8 k-steps over hd ----
        float s[2][8][4] = {};
        #pragma unroll
        for (int ks = 0; ks < 8; ks++) {
            const int kb = ks * 8;
            unsigned a[2][4];
            #pragma unroll
            for (int fm = 0; fm < 2; fm++) {
                const int mb = wm + fm * 16;
                a[fm][0] = __float_as_uint(Qs[(mb + grp) * QP + kb + tig]);
                a[fm][1] = __float_as_uint(Qs[(mb + grp + 8) * QP + kb + tig]);
                a[fm][2] = __float_as_uint(Qs[(mb + grp) * QP + kb + tig + 4]);
                a[fm][3] = __float_as_uint(Qs[(mb + grp + 8) * QP + kb + tig + 4]);
            }
            #pragma unroll
            for (int fn = 0; fn < 8; fn++) {
                unsigned b0 = __float_as_uint(Ks[(fn * 8 + grp) * KP + kb + tig]);
                unsigned b1 = __float_as_uint(Ks[(fn * 8 + grp) * KP + kb + tig + 4]);
                mma_tf32(s[0][fn], a[0], b0, b1);
                mma_tf32(s[1][fn], a[1], b0, b1);
            }
        }

        // ---- scale + causal mask ----
        const float sc = 0.125f;
        if (k0 + 63 > q0) {
            #pragma unroll
            for (int fm = 0; fm < 2; fm++) {
                const int ra = q0 + wm + fm * 16 + grp;
                const int rb = ra + 8;
                #pragma unroll
                for (int fn = 0; fn < 8; fn++) {
                    int kg = k0 + fn * 8 + tig * 2;
                    s[fm][fn][0] = (kg     > ra) ? -1e30f : s[fm][fn][0] * sc;
                    s[fm][fn][1] = (kg + 1 > ra) ? -1e30f : s[fm][fn][1] * sc;
                    s[fm][fn][2] = (kg     > rb) ? -1e30f : s[fm][fn][2] * sc;
                    s[fm][fn][3] = (kg + 1 > rb) ? -1e30f : s[fm][fn][3] * sc;
                }
            }
        } else {
            #pragma unroll
            for (int fm = 0; fm < 2; fm++)
                #pragma unroll
                for (int fn = 0; fn < 8; fn++) {
                    s[fm][fn][0] *= sc; s[fm][fn][1] *= sc;
                    s[fm][fn][2] *= sc; s[fm][fn][3] *= sc;
                }
        }

        // ---- online softmax (quad lanes share rows) ----
        #pragma unroll
        for (int fm = 0; fm < 2; fm++) {
            float ma = -INFINITY, mb = -INFINITY;
            #pragma unroll
            for (int fn = 0; fn < 8; fn++) {
                ma = fmaxf(ma, fmaxf(s[fm][fn][0], s[fm][fn][1]));
                mb = fmaxf(mb, fmaxf(s[fm][fn][2], s[fm][fn][3]));
            }
            ma = fmaxf(ma, __shfl_xor_sync(0xffffffffu, ma, 1));
            ma = fmaxf(ma, __shfl_xor_sync(0xffffffffu, ma, 2));
            mb = fmaxf(mb, __shfl_xor_sync(0xffffffffu, mb, 1));
            mb = fmaxf(mb, __shfl_xor_sync(0xffffffffu, mb, 2));

            float mna = fmaxf(mr[fm][0], ma);
            float mnb = fmaxf(mr[fm][1], mb);
            float ca  = __expf(mr[fm][0] - mna);
            float cb  = __expf(mr[fm][1] - mnb);

            float lsa = 0.f, lsb = 0.f;
            const int rowa = (wm + fm * 16 + grp) * PP;
            const int rowb = rowa + 8 * PP;
            #pragma unroll
            for (int fn = 0; fn < 8; fn++) {
                float p0 = __expf(s[fm][fn][0] - mna);
                float p1 = __expf(s[fm][fn][1] - mna);
                float p2 = __expf(s[fm][fn][2] - mnb);
                float p3 = __expf(s[fm][fn][3] - mnb);
                lsa += p0 + p1;
                lsb += p2 + p3;
                const int c = fn * 8 + tig * 2;
                float2 pa, pb;
                pa.x = __uint_as_float(f2tf32(p0));
                pa.y = __uint_as_float(f2tf32(p1));
                pb.x = __uint_as_float(f2tf32(p2));
                pb.y = __uint_as_float(f2tf32(p3));
                *(float2*)&Psall[warp * 32 * PP + rowa - (wm)*PP + c] = pa;  // == Ps[rowa_local]
                *(float2*)&Psall[warp * 32 * PP + rowb - (wm)*PP + c] = pb;
            }
            lsa += __shfl_xor_sync(0xffffffffu, lsa, 1);
            lsa += __shfl_xor_sync(0xffffffffu, lsa, 2);
            lsb += __shfl_xor_sync(0xffffffffu, lsb, 1);
            lsb += __shfl_xor_sync(0xffffffffu, lsb, 2);

            lr[fm][0] = lr[fm][0] * ca + lsa;
            lr[fm][1] = lr[fm][1] * cb + lsb;
            mr[fm][0] = mna;
            mr[fm][1] = mnb;

            #pragma unroll
            for (int fn = 0; fn < 8; fn++) {
                acc[fm][fn][0] *= ca; acc[fm][fn][1] *= ca;
                acc[fm][fn][2] *= cb; acc[fm][fn][3] *= cb;
            }
        }
        __syncwarp();   // Ps visible within warp

        // ---- O += P V : k = 64 keys, n = 64 hd ----
        #pragma unroll
        for (int ks = 0; ks < 8; ks++) {
            const int kb = ks * 8;
            unsigned a[2][4];
            #pragma unroll
            for (int fm = 0; fm < 2; fm++) {
                const int mb = fm * 16;
                a[fm][0] = __float_as_uint(Ps[(mb + grp) * PP + kb + tig]);
                a[fm][1] = __float_as_uint(Ps[(mb + grp + 8) * PP + kb + tig]);
                a[fm][2] = __float_as_uint(Ps[(mb + grp) * PP + kb + tig + 4]);
                a[fm][3] = __float_as_uint(Ps[(mb + grp + 8) * PP + kb + tig + 4]);
            }
            #pragma unroll
            for (int fn = 0; fn < 8; fn++) {
                unsigned b0 = __float_as_uint(Vs[(kb + tig) * VP + fn * 8 + grp]);
                unsigned b1 = __float_as_uint(Vs[(kb + tig + 4) * VP + fn * 8 + grp]);
                mma_tf32(acc[0][fn], a[0], b0, b1);
                mma_tf32(acc[1][fn], a[1], b0, b1);
            }
        }
        __syncwarp();   // done reading Ps before next iter overwrites
    }

    // ---- normalize + store ----
    #pragma unroll
    for (int fm = 0; fm < 2; fm++) {
        const int ra = q0 + wm + fm * 16 + grp;
        const int rb = ra + 8;
        float inva = 1.0f / lr[fm][0];
        float invb = 1.0f / lr[fm][1];
        #pragma unroll
        for (int fn = 0; fn < 8; fn++) {
            const int c0 = col0 + fn * 8 + tig * 2;
            float2 oa, ob;
            oa.x = acc[fm][fn][0] * inva;
            oa.y = acc[fm][fn][1] * inva;
            ob.x = acc[fm][fn][2] * invb;
            ob.y = acc[fm][fn][3] * invb;
            *(float2*)(O + (row_base + ra) * DD + c0) = oa;
            *(float2*)(O + (row_base + rb) * DD + c0) = ob;
        }
    }
}

// ---------------------------------------------------------------------------
extern "C" void kernel_launch(void* const* d_in, const int* in_sizes, int n_in,
                              void* d_out, int out_size)
{
    const float* x  = (const float*)d_in[0];
    const float* Wq = (const float*)d_in[1];
    const float* bq = (const float*)d_in[2];
    const float* Wk = (const float*)d_in[3];
    const float* bk = (const float*)d_in[4];
    const float* Wv = (const float*)d_in[5];
    const float* bv = (const float*)d_in[6];
    const float* Wp = (const float*)d_in[7];
    const float* bp = (const float*)d_in[8];
    float* out = (float*)d_out;

    float *Qp, *Kp, *Vp, *Op;
    cudaGetSymbolAddress((void**)&Qp, g_Q);
    cudaGetSymbolAddress((void**)&Kp, g_K);
    cudaGetSymbolAddress((void**)&Vp, g_V);
    cudaGetSymbolAddress((void**)&Op, g_O);

    dim3 gemm_grid(DD / 128, MM / 128);   // (8, 64)
    gemm_tf32<<<gemm_grid, 256>>>(x, Wq, bq, Qp, MM, DD, DD);
    gemm_tf32<<<gemm_grid, 256>>>(x, Wk, bk, Kp, MM, DD, DD);
    gemm_tf32<<<gemm_grid, 256>>>(x, Wv, bv, Vp, MM, DD, DD);

    static bool attr_set = false;
    if (!attr_set) {
        cudaFuncSetAttribute(attn_tc,
                             cudaFuncAttributeMaxDynamicSharedMemorySize, ATT_SMEM);
        attr_set = true;
    }
    dim3 attn_grid(SS / 128, HH, BB);    // (16, 16, 4)
    attn_tc<<<attn_grid, 128, ATT_SMEM>>>(Qp, Kp, Vp, Op);

    gemm_tf32<<<gemm_grid, 256>>>(Op, Wp, bp, out, MM, DD, DD);
}